// round 2
// baseline (speedup 1.0000x reference)
#include <cuda_runtime.h>

#define NSMP   8192
#define NA     512
#define DOUT   256
#define PITCH  8712   // input row length = REALNA + NSMP
#define ACOL0  512    // A starts at input col 512 (= realna - 8)
#define OPITCH 8448   // output row length = DOUT + NSMP

// Scratch (static device globals — no runtime allocation)
__device__ float g_part[64 * NSMP];        // partial column sums
__device__ float g_dinv[NSMP];             // rsqrt(degree)
__device__ float g_support[NSMP * DOUT];   // dinv[j] * (X @ W)[j,k]

// ---------------------------------------------------------------------------
// Kernel 1: partial column sums of A. grid (32 col-blocks, 64 row-chunks).
// Deterministic (no atomics): each (colblk, rowchunk) writes its own slot.
// ---------------------------------------------------------------------------
__global__ void colsum_part(const float* __restrict__ in) {
    int col = blockIdx.x * 256 + threadIdx.x;
    int r0  = blockIdx.y * 128;
    const float* p = in + (size_t)r0 * PITCH + ACOL0 + col;
    float s = 0.f;
    #pragma unroll 8
    for (int r = 0; r < 128; ++r) { s += *p; p += PITCH; }
    g_part[blockIdx.y * NSMP + col] = s;
}

// ---------------------------------------------------------------------------
// Kernel 2: reduce partials, add identity contribution (+1), rsqrt.
// ---------------------------------------------------------------------------
__global__ void finalize_d() {
    int col = blockIdx.x * 256 + threadIdx.x;
    float s = 1.0f;  // the +I diagonal contributes 1 to every column sum
    #pragma unroll
    for (int i = 0; i < 64; ++i) s += g_part[i * NSMP + col];
    g_dinv[col] = rsqrtf(s);
}

// ---------------------------------------------------------------------------
// Kernel 3: support' = diag(dinv) * (X @ W).  M=8192, K=512, N=256.
// 64x64 tiles, 256 threads, 4x4 micro-tile, K-tile 16.
// ---------------------------------------------------------------------------
__global__ void support_gemm(const float* __restrict__ in, const float* __restrict__ w) {
    __shared__ float Xs[16][65];   // transposed: Xs[k][row], +1 pad
    __shared__ float Ws[16][64];
    int tid = threadIdx.x;
    int tx = tid % 16, ty = tid / 16;
    int m0 = blockIdx.x * 64;
    int n0 = blockIdx.y * 64;
    float acc[4][4] = {};

    for (int k0 = 0; k0 < NA; k0 += 16) {
        {   // X tile 64x16 -> transposed
            int k = tid % 16;
            int r = tid / 16;
            #pragma unroll
            for (int i = 0; i < 4; ++i)
                Xs[k][r + 16 * i] = in[(size_t)(m0 + r + 16 * i) * PITCH + k0 + k];
        }
        {   // W tile 16x64
            int c  = tid % 64;
            int kk = tid / 64;
            #pragma unroll
            for (int i = 0; i < 4; ++i)
                Ws[kk + 4 * i][c] = w[(size_t)(k0 + kk + 4 * i) * DOUT + n0 + c];
        }
        __syncthreads();
        #pragma unroll
        for (int kk = 0; kk < 16; ++kk) {
            float a[4], b[4];
            #pragma unroll
            for (int i = 0; i < 4; ++i) a[i] = Xs[kk][ty * 4 + i];
            #pragma unroll
            for (int j = 0; j < 4; ++j) b[j] = Ws[kk][tx * 4 + j];
            #pragma unroll
            for (int i = 0; i < 4; ++i)
                #pragma unroll
                for (int j = 0; j < 4; ++j)
                    acc[i][j] += a[i] * b[j];
        }
        __syncthreads();
    }
    #pragma unroll
    for (int i = 0; i < 4; ++i) {
        int row = m0 + ty * 4 + i;
        float dv = g_dinv[row];   // fold dis_j into B operand of the big GEMM
        #pragma unroll
        for (int j = 0; j < 4; ++j)
            g_support[(size_t)row * DOUT + n0 + tx * 4 + j] = dv * acc[i][j];
    }
}

// ---------------------------------------------------------------------------
// Kernel 4: out[:, :256] = diag(dinv) * (A+I) @ support'
//           out[:, 256:] = A+I   (fused into the A-tile load — A read once)
// M-tile 32 x full N=256, K-tile 32. 256 threads, 4x8 micro-tile.
// ---------------------------------------------------------------------------
__global__ void main_gemm(const float* __restrict__ in, float* __restrict__ out) {
    __shared__ float As[32][33];    // As[kk][row], +1 pad (conflict-free)
    __shared__ float Bs[32][DOUT];  // 32 KB
    int tid = threadIdx.x;
    int tx = tid % 32, ty = tid / 32;     // ty in 0..7
    int m0 = blockIdx.x * 32;
    float acc[4][8] = {};

    for (int k0 = 0; k0 < NSMP; k0 += 32) {
        {   // A tile 32x32: load, add identity, write out[:,256:], stash transposed
            int c  = tid % 32;
            int r4 = tid / 32;
            #pragma unroll
            for (int i = 0; i < 4; ++i) {
                int r    = r4 + 8 * i;
                int grow = m0 + r;
                int gcol = k0 + c;
                float v = in[(size_t)grow * PITCH + ACOL0 + gcol];
                v += (grow == gcol) ? 1.0f : 0.0f;
                out[(size_t)grow * OPITCH + DOUT + gcol] = v;
                As[c][r] = v;
            }
        }
        {   // B tile 32x256 via float4 (coalesced)
            const float4* bsrc = (const float4*)(g_support + (size_t)k0 * DOUT);
            float4* bdst = (float4*)(&Bs[0][0]);
            #pragma unroll
            for (int i = 0; i < 8; ++i)
                bdst[tid + 256 * i] = bsrc[tid + 256 * i];
        }
        __syncthreads();
        #pragma unroll
        for (int kk = 0; kk < 32; ++kk) {
            float a[4], b[8];
            #pragma unroll
            for (int i = 0; i < 4; ++i) a[i] = As[kk][ty * 4 + i];      // broadcast
            #pragma unroll
            for (int j = 0; j < 8; ++j) b[j] = Bs[kk][tx + 32 * j];     // bank = lane
            #pragma unroll
            for (int i = 0; i < 4; ++i)
                #pragma unroll
                for (int j = 0; j < 8; ++j)
                    acc[i][j] += a[i] * b[j];
        }
        __syncthreads();
    }
    #pragma unroll
    for (int i = 0; i < 4; ++i) {
        int row = m0 + ty * 4 + i;
        float dv = g_dinv[row];
        #pragma unroll
        for (int j = 0; j < 8; ++j)
            out[(size_t)row * OPITCH + tx + 32 * j] = dv * acc[i][j];
    }
}

// ---------------------------------------------------------------------------
extern "C" void kernel_launch(void* const* d_in, const int* in_sizes, int n_in,
                              void* d_out, int out_size) {
    const float* in = (const float*)d_in[0];
    const float* w  = (const float*)d_in[1];
    float* out = (float*)d_out;

    colsum_part <<<dim3(32, 64), 256>>>(in);
    finalize_d  <<<32, 256>>>();
    support_gemm<<<dim3(128, 4), 256>>>(in, w);
    main_gemm   <<<256, 256>>>(in, out);
}

// round 4
// speedup vs baseline: 3.4329x; 3.4329x over previous
#include <cuda_runtime.h>
#include <cuda_bf16.h>
#include <cstdint>

#define NSMP   8192
#define NA     512
#define DOUT   256
#define PITCH  8712   // input row length
#define ACOL0  512    // A starts at input col 512
#define OPITCH 8448   // output row length

// Scratch (static device globals — no runtime allocation)
__device__ float g_part[64 * NSMP];
__device__ float g_dinv[NSMP];
__device__ __align__(16) __nv_bfloat16 g_supT[(size_t)DOUT * NSMP]; // S_T[n][j]=dinv[j]*(X@W)[j,n]

// ---------------------------------------------------------------------------
// PTX helpers (base-target-safe: mma.sync / ldmatrix / cp.async only)
// ---------------------------------------------------------------------------
__device__ __forceinline__ uint32_t s2u(const void* p) {
    return (uint32_t)__cvta_generic_to_shared(p);
}
__device__ __forceinline__ void cp_async16(uint32_t s, const void* g) {
    asm volatile("cp.async.cg.shared.global [%0], [%1], 16;" :: "r"(s), "l"(g) : "memory");
}
__device__ __forceinline__ void cp_commit() {
    asm volatile("cp.async.commit_group;" ::: "memory");
}
template <int N>
__device__ __forceinline__ void cp_wait() {
    asm volatile("cp.async.wait_group %0;" :: "n"(N) : "memory");
}
__device__ __forceinline__ void ldsm4(uint32_t* r, uint32_t addr) {
    asm volatile("ldmatrix.sync.aligned.m8n8.x4.shared.b16 {%0,%1,%2,%3}, [%4];"
                 : "=r"(r[0]), "=r"(r[1]), "=r"(r[2]), "=r"(r[3]) : "r"(addr));
}
__device__ __forceinline__ void mma16816(float* d, const uint32_t* a, uint32_t b0, uint32_t b1) {
    asm volatile(
        "mma.sync.aligned.m16n8k16.row.col.f32.bf16.bf16.f32 "
        "{%0,%1,%2,%3}, {%4,%5,%6,%7}, {%8,%9}, {%0,%1,%2,%3};"
        : "+f"(d[0]), "+f"(d[1]), "+f"(d[2]), "+f"(d[3])
        : "r"(a[0]), "r"(a[1]), "r"(a[2]), "r"(a[3]), "r"(b0), "r"(b1));
}

// ---------------------------------------------------------------------------
// Kernel 1: partial column sums of A (deterministic, no atomics)
// ---------------------------------------------------------------------------
__global__ void colsum_part(const float* __restrict__ in) {
    int col = blockIdx.x * 256 + threadIdx.x;
    int r0  = blockIdx.y * 128;
    const float* p = in + (size_t)r0 * PITCH + ACOL0 + col;
    float s = 0.f;
    #pragma unroll 8
    for (int r = 0; r < 128; ++r) { s += *p; p += PITCH; }
    g_part[blockIdx.y * NSMP + col] = s;
}

// ---------------------------------------------------------------------------
// Kernel 2: reduce partials, +1 (identity), rsqrt
// ---------------------------------------------------------------------------
__global__ void finalize_d() {
    int col = blockIdx.x * 256 + threadIdx.x;
    float s = 1.0f;
    #pragma unroll
    for (int i = 0; i < 64; ++i) s += g_part[i * NSMP + col];
    g_dinv[col] = rsqrtf(s);
}

// ---------------------------------------------------------------------------
// Kernel 3: S_T[n][j] = bf16( dinv[j] * (X @ W)[j,n] )   (transposed store)
// ---------------------------------------------------------------------------
__global__ void support_gemm(const float* __restrict__ in, const float* __restrict__ w) {
    __shared__ float Xs[16][65];
    __shared__ float Ws[16][64];
    __shared__ __align__(16) __nv_bfloat16 Ts[64][80];  // pitch 160B (16B-multiple)
    int tid = threadIdx.x;
    int tx = tid % 16, ty = tid / 16;
    int m0 = blockIdx.x * 64;
    int n0 = blockIdx.y * 64;
    float acc[4][4] = {};

    for (int k0 = 0; k0 < NA; k0 += 16) {
        {
            int k = tid % 16;
            int r = tid / 16;
            #pragma unroll
            for (int i = 0; i < 4; ++i)
                Xs[k][r + 16 * i] = in[(size_t)(m0 + r + 16 * i) * PITCH + k0 + k];
        }
        {
            int c  = tid % 64;
            int kk = tid / 64;
            #pragma unroll
            for (int i = 0; i < 4; ++i)
                Ws[kk + 4 * i][c] = w[(size_t)(k0 + kk + 4 * i) * DOUT + n0 + c];
        }
        __syncthreads();
        #pragma unroll
        for (int kk = 0; kk < 16; ++kk) {
            float a[4], b[4];
            #pragma unroll
            for (int i = 0; i < 4; ++i) a[i] = Xs[kk][ty * 4 + i];
            #pragma unroll
            for (int j = 0; j < 4; ++j) b[j] = Ws[kk][tx * 4 + j];
            #pragma unroll
            for (int i = 0; i < 4; ++i)
                #pragma unroll
                for (int j = 0; j < 4; ++j)
                    acc[i][j] += a[i] * b[j];
        }
        __syncthreads();
    }
    // transpose through smem, fold dinv[j], store bf16 coalesced
    #pragma unroll
    for (int i = 0; i < 4; ++i) {
        float dv = g_dinv[m0 + ty * 4 + i];
        #pragma unroll
        for (int j = 0; j < 4; ++j)
            Ts[tx * 4 + j][ty * 4 + i] = __float2bfloat16(dv * acc[i][j]);
    }
    __syncthreads();
    {
        int rn = tid >> 2, s = tid & 3;
        uint4* dst = (uint4*)(g_supT + (size_t)(n0 + rn) * NSMP + m0 + s * 16);
        const uint4* src = (const uint4*)(&Ts[rn][s * 16]);
        dst[0] = src[0];
        dst[1] = src[1];
    }
}

// ---------------------------------------------------------------------------
// Kernel 4 (mma.sync bf16): out[:, :256] = diag(dinv) * (A+I) @ S
//                           out[:, 256:] = A+I  (fused into A-tile path)
// CTA tile 64x256, K-tile 64, double-buffered. 8 warps (2M x 4N), warp 32x64.
// ---------------------------------------------------------------------------
#define KT 64
#define SM_A0 0
#define SM_B0 8192
#define SM_A1 40960
#define SM_B1 49152
#define SMEM_TOTAL 81920

// SW128-swizzled smem offset for (row, 16B-chunk c) with 128B rows
__device__ __forceinline__ uint32_t swz(int row, int c) {
    return (uint32_t)(row * 128 + ((c ^ (row & 7)) << 4));
}

struct MG {
    const float* aig;  // input A base for this thread
    float* aog;        // output A+I base for this thread
    int f, r0, m0;
};

__device__ __forceinline__ void load_tile(const MG& g, char* smem, int buf, int k0,
                                          int tid) {
    // B tile: 256 x 64 bf16 = 32 KB via cp.async, SW128 swizzled
    uint32_t bs = s2u(smem + (buf ? SM_B1 : SM_B0));
    const char* gB = (const char*)g_supT + (size_t)k0 * 2;
    #pragma unroll
    for (int c = 0; c < 8; ++c) {
        int chunk = tid + c * 256;       // 0..2047
        int row = chunk >> 3;            // n: 0..255
        int seg = chunk & 7;             // 16B segment
        cp_async16(bs + swz(row, seg), gB + (size_t)row * (NSMP * 2) + seg * 16);
    }
    cp_commit();

    // A tile: 64 x 64 fp32: LDG.128, +I, fused STG of A+I, cvt bf16, swizzled STS
    char* As = smem + (buf ? SM_A1 : SM_A0);
    #pragma unroll
    for (int i = 0; i < 4; ++i) {
        int row  = g.r0 + 16 * i;
        int grow = g.m0 + row;
        float4 v = *(const float4*)(g.aig + (size_t)16 * i * PITCH + k0);
        int gc0 = k0 + g.f * 4;
        if (grow == gc0    ) v.x += 1.f;
        if (grow == gc0 + 1) v.y += 1.f;
        if (grow == gc0 + 2) v.z += 1.f;
        if (grow == gc0 + 3) v.w += 1.f;
        *(float4*)(g.aog + (size_t)16 * i * OPITCH + k0) = v;
        __nv_bfloat162 h0 = __floats2bfloat162_rn(v.x, v.y);
        __nv_bfloat162 h1 = __floats2bfloat162_rn(v.z, v.w);
        uint32_t off = swz(row, g.f >> 1) + (g.f & 1) * 8;
        *(uint2*)(As + off) = make_uint2(*(uint32_t*)&h0, *(uint32_t*)&h1);
    }
}

__global__ void __launch_bounds__(256, 2) main_gemm_mma(const float* __restrict__ in,
                                                        float* __restrict__ out) {
    extern __shared__ char smem[];
    int tid = threadIdx.x;
    int wid = tid >> 5, lane = tid & 31;
    int m0 = blockIdx.x * 64;

    int warp_m = (wid & 1) * 32;
    int warp_n = (wid >> 1) * 64;

    MG g;
    g.f = tid & 15;
    g.r0 = tid >> 4;
    g.m0 = m0;
    g.aig = in  + (size_t)(m0 + g.r0) * PITCH  + ACOL0 + g.f * 4;
    g.aog = out + (size_t)(m0 + g.r0) * OPITCH + DOUT  + g.f * 4;

    // ldmatrix per-lane rows (fixed across k-steps)
    int rowA[2], rowB[4];
    #pragma unroll
    for (int mi = 0; mi < 2; ++mi) rowA[mi] = warp_m + mi * 16 + (lane & 15);
    int hiA = lane >> 4;                       // 0/1 -> k chunk +0/+16B
    #pragma unroll
    for (int nb = 0; nb < 4; ++nb)
        rowB[nb] = warp_n + nb * 16 + ((lane >> 4) << 3) + (lane & 7);
    int hiB = (lane >> 3) & 1;

    float acc[2][8][4];
    #pragma unroll
    for (int i = 0; i < 2; ++i)
        #pragma unroll
        for (int j = 0; j < 8; ++j)
            #pragma unroll
            for (int c = 0; c < 4; ++c) acc[i][j][c] = 0.f;

    // prologue
    load_tile(g, smem, 0, 0, tid);

    for (int it = 0; it < NSMP / KT; ++it) {
        int buf = it & 1;
        if (it + 1 < NSMP / KT) {
            load_tile(g, smem, buf ^ 1, (it + 1) * KT, tid);
            cp_wait<1>();
        } else {
            cp_wait<0>();
        }
        __syncthreads();

        uint32_t As = s2u(smem + (buf ? SM_A1 : SM_A0));
        uint32_t Bs = s2u(smem + (buf ? SM_B1 : SM_B0));

        #pragma unroll
        for (int kk = 0; kk < 4; ++kk) {
            uint32_t a[2][4];
            #pragma unroll
            for (int mi = 0; mi < 2; ++mi)
                ldsm4(a[mi], As + swz(rowA[mi], kk * 2 + hiA));
            #pragma unroll
            for (int nb = 0; nb < 4; ++nb) {
                uint32_t b[4];
                ldsm4(b, Bs + swz(rowB[nb], kk * 2 + hiB));
                mma16816(acc[0][2 * nb],     a[0], b[0], b[1]);
                mma16816(acc[0][2 * nb + 1], a[0], b[2], b[3]);
                mma16816(acc[1][2 * nb],     a[1], b[0], b[1]);
                mma16816(acc[1][2 * nb + 1], a[1], b[2], b[3]);
            }
        }
        __syncthreads();
    }

    // epilogue: scale by dinv[row], store out[:, :256]
    int qr = lane >> 2;          // 0..7
    int qc = (lane & 3) * 2;
    #pragma unroll
    for (int mi = 0; mi < 2; ++mi) {
        int r0g = m0 + warp_m + mi * 16 + qr;
        float dv0 = g_dinv[r0g];
        float dv1 = g_dinv[r0g + 8];
        float* o0 = out + (size_t)r0g * OPITCH;
        float* o1 = o0 + (size_t)8 * OPITCH;
        #pragma unroll
        for (int n8 = 0; n8 < 8; ++n8) {
            int col = warp_n + n8 * 8 + qc;
            o0[col]     = dv0 * acc[mi][n8][0];
            o0[col + 1] = dv0 * acc[mi][n8][1];
            o1[col]     = dv1 * acc[mi][n8][2];
            o1[col + 1] = dv1 * acc[mi][n8][3];
        }
    }
}

// ---------------------------------------------------------------------------
extern "C" void kernel_launch(void* const* d_in, const int* in_sizes, int n_in,
                              void* d_out, int out_size) {
    const float* in = (const float*)d_in[0];
    const float* w  = (const float*)d_in[1];
    float* out = (float*)d_out;

    cudaFuncSetAttribute(main_gemm_mma, cudaFuncAttributeMaxDynamicSharedMemorySize, SMEM_TOTAL);

    colsum_part  <<<dim3(32, 64), 256>>>(in);
    finalize_d   <<<32, 256>>>();
    support_gemm <<<dim3(128, 4), 256>>>(in, w);
    main_gemm_mma<<<128, 256, SMEM_TOTAL>>>(in, out);
}

// round 5
// speedup vs baseline: 5.2874x; 1.5402x over previous
#include <cuda_runtime.h>
#include <cuda_bf16.h>
#include <cstdint>

#define NSMP   8192
#define NA     512
#define DOUT   256
#define PITCH  8712   // input row length
#define ACOL0  512    // A starts at input col 512
#define OPITCH 8448   // output row length

// Scratch (static device globals — no runtime allocation)
__device__ float g_part[64 * NSMP];
__device__ float g_dinv[NSMP];
__device__ __align__(16) __nv_bfloat16 g_supT[(size_t)DOUT * NSMP]; // S_T[n][j]
__device__ __align__(16) __nv_bfloat16 g_WT[(size_t)DOUT * NA];     // W^T[n][k] bf16

// ---------------------------------------------------------------------------
// PTX helpers (base-target-safe)
// ---------------------------------------------------------------------------
__device__ __forceinline__ uint32_t s2u(const void* p) {
    return (uint32_t)__cvta_generic_to_shared(p);
}
__device__ __forceinline__ void cp_async16(uint32_t s, const void* g) {
    asm volatile("cp.async.cg.shared.global [%0], [%1], 16;" :: "r"(s), "l"(g) : "memory");
}
__device__ __forceinline__ void cp_commit() {
    asm volatile("cp.async.commit_group;" ::: "memory");
}
template <int N>
__device__ __forceinline__ void cp_wait() {
    asm volatile("cp.async.wait_group %0;" :: "n"(N) : "memory");
}
__device__ __forceinline__ void ldsm4(uint32_t* r, uint32_t addr) {
    asm volatile("ldmatrix.sync.aligned.m8n8.x4.shared.b16 {%0,%1,%2,%3}, [%4];"
                 : "=r"(r[0]), "=r"(r[1]), "=r"(r[2]), "=r"(r[3]) : "r"(addr));
}
__device__ __forceinline__ void mma16816(float* d, const uint32_t* a, uint32_t b0, uint32_t b1) {
    asm volatile(
        "mma.sync.aligned.m16n8k16.row.col.f32.bf16.bf16.f32 "
        "{%0,%1,%2,%3}, {%4,%5,%6,%7}, {%8,%9}, {%0,%1,%2,%3};"
        : "+f"(d[0]), "+f"(d[1]), "+f"(d[2]), "+f"(d[3])
        : "r"(a[0]), "r"(a[1]), "r"(a[2]), "r"(a[3]), "r"(b0), "r"(b1));
}
// SW128-swizzled smem offset for (row, 16B-chunk c) with 128B rows
__device__ __forceinline__ uint32_t swz(int row, int c) {
    return (uint32_t)(row * 128 + ((c ^ (row & 7)) << 4));
}

// ---------------------------------------------------------------------------
// Kernel: W^T bf16 (tiny, independent)
// ---------------------------------------------------------------------------
__global__ void wt_kernel(const float* __restrict__ w) {
    __shared__ float ts[32][33];
    int k0 = blockIdx.x * 32, n0 = blockIdx.y * 32;
    int t = threadIdx.x;
    int a = t >> 5, b = t & 31;
    #pragma unroll
    for (int i = 0; i < 4; ++i)
        ts[a + 8 * i][b] = w[(size_t)(k0 + a + 8 * i) * DOUT + n0 + b];
    __syncthreads();
    #pragma unroll
    for (int i = 0; i < 4; ++i)
        g_WT[(size_t)(n0 + a + 8 * i) * NA + k0 + b] = __float2bfloat16(ts[b][a + 8 * i]);
}

// ---------------------------------------------------------------------------
// Kernel: partial column sums of A (float4, deterministic)
// ---------------------------------------------------------------------------
__global__ void colsum_part(const float* __restrict__ in) {
    int col = (blockIdx.x * 256 + threadIdx.x) * 4;
    int r0  = blockIdx.y * 128;
    const float* p = in + (size_t)r0 * PITCH + ACOL0 + col;
    float4 s = make_float4(0.f, 0.f, 0.f, 0.f);
    #pragma unroll 8
    for (int r = 0; r < 128; ++r) {
        float4 v = *(const float4*)p;
        s.x += v.x; s.y += v.y; s.z += v.z; s.w += v.w;
        p += PITCH;
    }
    *(float4*)(g_part + blockIdx.y * NSMP + col) = s;
}

__global__ void finalize_d() {
    int col = blockIdx.x * 256 + threadIdx.x;
    float s = 1.0f;
    #pragma unroll
    for (int i = 0; i < 64; ++i) s += g_part[i * NSMP + col];
    g_dinv[col] = rsqrtf(s);
}

// ---------------------------------------------------------------------------
// support (mma.sync): S_T[n][j] = bf16( dinv[j] * (X @ W)[j,n] )
// CTA 64x256, K=512 (8 k-tiles of 64), grid 128. Clone of R4 main structure.
// ---------------------------------------------------------------------------
#define SP_A0 0
#define SP_B0 8192
#define SP_A1 40960
#define SP_B1 49152
#define SP_TOTAL 81920
#define ST_PITCH 144   // staging pitch bytes (16B-multiple, bank-spread)

__device__ __forceinline__ void sp_load(const float* in, char* smem, int buf, int k0,
                                        int tid, int m0) {
    // B tile: 256 x 64 bf16 from g_WT (row pitch 1024B)
    uint32_t bs = s2u(smem + (buf ? SP_B1 : SP_B0));
    const char* gB = (const char*)g_WT + (size_t)k0 * 2;
    #pragma unroll
    for (int c = 0; c < 8; ++c) {
        int chunk = tid + c * 256;
        int row = chunk >> 3;
        int seg = chunk & 7;
        cp_async16(bs + swz(row, seg), gB + (size_t)row * (NA * 2) + seg * 16);
    }
    cp_commit();
    // A tile (X): 64x64 fp32 -> bf16 swizzled STS
    char* As = smem + (buf ? SP_A1 : SP_A0);
    int f = tid & 15, r0 = tid >> 4;
    #pragma unroll
    for (int i = 0; i < 4; ++i) {
        int row = r0 + 16 * i;
        float4 v = *(const float4*)(in + (size_t)(m0 + row) * PITCH + k0 + f * 4);
        __nv_bfloat162 h0 = __floats2bfloat162_rn(v.x, v.y);
        __nv_bfloat162 h1 = __floats2bfloat162_rn(v.z, v.w);
        *(uint2*)(As + swz(row, f >> 1) + (f & 1) * 8) =
            make_uint2(*(uint32_t*)&h0, *(uint32_t*)&h1);
    }
}

__global__ void __launch_bounds__(256, 1) support_mma(const float* __restrict__ in) {
    extern __shared__ char smem[];
    int tid = threadIdx.x;
    int wid = tid >> 5, lane = tid & 31;
    int m0 = blockIdx.x * 64;
    int warp_m = (wid & 1) * 32;
    int warp_n = (wid >> 1) * 64;

    int rowA[2], rowB[4];
    #pragma unroll
    for (int mi = 0; mi < 2; ++mi) rowA[mi] = warp_m + mi * 16 + (lane & 15);
    int hiA = lane >> 4;
    #pragma unroll
    for (int nb = 0; nb < 4; ++nb)
        rowB[nb] = warp_n + nb * 16 + ((lane >> 4) << 3) + (lane & 7);
    int hiB = (lane >> 3) & 1;

    float acc[2][8][4] = {};

    sp_load(in, smem, 0, 0, tid, m0);
    for (int it = 0; it < NA / 64; ++it) {
        int buf = it & 1;
        if (it + 1 < NA / 64) { sp_load(in, smem, buf ^ 1, (it + 1) * 64, tid, m0); cp_wait<1>(); }
        else cp_wait<0>();
        __syncthreads();
        uint32_t As = s2u(smem + (buf ? SP_A1 : SP_A0));
        uint32_t Bs = s2u(smem + (buf ? SP_B1 : SP_B0));
        #pragma unroll
        for (int kk = 0; kk < 4; ++kk) {
            uint32_t a[2][4];
            #pragma unroll
            for (int mi = 0; mi < 2; ++mi)
                ldsm4(a[mi], As + swz(rowA[mi], kk * 2 + hiA));
            #pragma unroll
            for (int nb = 0; nb < 4; ++nb) {
                uint32_t b[4];
                ldsm4(b, Bs + swz(rowB[nb], kk * 2 + hiB));
                mma16816(acc[0][2 * nb],     a[0], b[0], b[1]);
                mma16816(acc[0][2 * nb + 1], a[0], b[2], b[3]);
                mma16816(acc[1][2 * nb],     a[1], b[0], b[1]);
                mma16816(acc[1][2 * nb + 1], a[1], b[2], b[3]);
            }
        }
        __syncthreads();
    }

    // epilogue: scale by dinv[j], bf16, stage transposed [n][j], STG coalesced
    int qr = lane >> 2, qc = (lane & 3) * 2;
    #pragma unroll
    for (int mi = 0; mi < 2; ++mi) {
        int j0 = warp_m + mi * 16 + qr;
        float dv0 = g_dinv[m0 + j0];
        float dv1 = g_dinv[m0 + j0 + 8];
        #pragma unroll
        for (int n8 = 0; n8 < 8; ++n8) {
            int n = warp_n + n8 * 8 + qc;
            *(__nv_bfloat16*)(smem + n * ST_PITCH + j0 * 2)             = __float2bfloat16(dv0 * acc[mi][n8][0]);
            *(__nv_bfloat16*)(smem + (n + 1) * ST_PITCH + j0 * 2)       = __float2bfloat16(dv0 * acc[mi][n8][1]);
            *(__nv_bfloat16*)(smem + n * ST_PITCH + (j0 + 8) * 2)       = __float2bfloat16(dv1 * acc[mi][n8][2]);
            *(__nv_bfloat16*)(smem + (n + 1) * ST_PITCH + (j0 + 8) * 2) = __float2bfloat16(dv1 * acc[mi][n8][3]);
        }
    }
    __syncthreads();
    #pragma unroll
    for (int c = 0; c < 8; ++c) {
        int chunk = tid + c * 256;
        int n = chunk >> 3;
        int seg = chunk & 7;
        uint4 v = *(const uint4*)(smem + n * ST_PITCH + seg * 16);
        *(uint4*)((char*)g_supT + ((size_t)n * NSMP + m0) * 2 + seg * 16) = v;
    }
}

// ---------------------------------------------------------------------------
// main (mma.sync): out[:, :256] = diag(dinv) * (A+I) @ S ; out[:, 256:] = A+I
// CTA 32x256, grid 256 (2 CTAs/SM), K-tile 64, all loads cp.async.
// ---------------------------------------------------------------------------
#define MB0  0
#define MB1  32768
#define MAR0 65536
#define MAR1 73728
#define MAF0 81920
#define MAF1 86016
#define MG_TOTAL 90112

__device__ __forceinline__ void mg_load(const float* in, char* smem, int buf, int k0,
                                        int tid, int m0) {
    // B tile: 256 x 64 bf16 from g_supT (row pitch NSMP*2)
    uint32_t bs = s2u(smem + (buf ? MB1 : MB0));
    const char* gB = (const char*)g_supT + (size_t)k0 * 2;
    #pragma unroll
    for (int c = 0; c < 8; ++c) {
        int chunk = tid + c * 256;
        int row = chunk >> 3;
        int seg = chunk & 7;
        cp_async16(bs + swz(row, seg), gB + (size_t)row * (NSMP * 2) + seg * 16);
    }
    // A raw fp32 tile 32x64 (8KB), XOR-swizzled chunks
    uint32_t ar = s2u(smem + (buf ? MAR1 : MAR0));
    int r = tid >> 3, c = tid & 7;
    int p = c ^ (r & 7);
    const char* gA = (const char*)(in + (size_t)(m0 + r) * PITCH + ACOL0 + k0);
    cp_async16(ar + r * 256 + p * 16,       gA + c * 16);
    cp_async16(ar + r * 256 + (p + 8) * 16, gA + (c + 8) * 16);
    cp_commit();
}

__global__ void __launch_bounds__(256, 2) main_gemm2(const float* __restrict__ in,
                                                     float* __restrict__ out) {
    extern __shared__ char smem[];
    int tid = threadIdx.x;
    int wid = tid >> 5, lane = tid & 31;
    int m0 = blockIdx.x * 32;
    int warp_n = wid * 32;

    int rowA[2], rowB[2];
    #pragma unroll
    for (int mi = 0; mi < 2; ++mi) rowA[mi] = mi * 16 + (lane & 15);
    int hiA = lane >> 4;
    #pragma unroll
    for (int nb = 0; nb < 2; ++nb)
        rowB[nb] = warp_n + nb * 16 + ((lane >> 4) << 3) + (lane & 7);
    int hiB = (lane >> 3) & 1;

    float acc[2][4][4] = {};

    int pr = tid >> 3, ps = tid & 7;  // processA mapping
    float* aog = out + (size_t)(m0 + pr) * OPITCH + DOUT + ps * 4;

    mg_load(in, smem, 0, 0, tid, m0);

    for (int it = 0; it < NSMP / 64; ++it) {
        int buf = it & 1;
        if (it + 1 < NSMP / 64) { mg_load(in, smem, buf ^ 1, (it + 1) * 64, tid, m0); cp_wait<1>(); }
        else cp_wait<0>();
        __syncthreads();
        int k0 = it * 64;

        // processA: smem fp32 -> +I -> fused A+I copy-out -> bf16 swizzled STS
        {
            const char* ar = smem + (buf ? MAR1 : MAR0);
            char* af = smem + (buf ? MAF1 : MAF0);
            int p = ps ^ (pr & 7);
            float4 v0 = *(const float4*)(ar + pr * 256 + p * 16);
            float4 v1 = *(const float4*)(ar + pr * 256 + (p + 8) * 16);
            int grow = m0 + pr;
            int d0 = grow - (k0 + 4 * ps);
            int d1 = d0 - 32;
            if ((unsigned)d0 < 4u) ((float*)&v0)[d0] += 1.f;
            if ((unsigned)d1 < 4u) ((float*)&v1)[d1] += 1.f;
            *(float4*)(aog + k0)      = v0;
            *(float4*)(aog + k0 + 32) = v1;
            __nv_bfloat162 h0 = __floats2bfloat162_rn(v0.x, v0.y);
            __nv_bfloat162 h1 = __floats2bfloat162_rn(v0.z, v0.w);
            __nv_bfloat162 h2 = __floats2bfloat162_rn(v1.x, v1.y);
            __nv_bfloat162 h3 = __floats2bfloat162_rn(v1.z, v1.w);
            *(uint2*)(af + swz(pr, ps >> 1) + (ps & 1) * 8) =
                make_uint2(*(uint32_t*)&h0, *(uint32_t*)&h1);
            *(uint2*)(af + swz(pr, 4 + (ps >> 1)) + (ps & 1) * 8) =
                make_uint2(*(uint32_t*)&h2, *(uint32_t*)&h3);
        }
        __syncthreads();

        uint32_t Af = s2u(smem + (buf ? MAF1 : MAF0));
        uint32_t Bs = s2u(smem + (buf ? MB1 : MB0));
        #pragma unroll
        for (int kk = 0; kk < 4; ++kk) {
            uint32_t a[2][4];
            #pragma unroll
            for (int mi = 0; mi < 2; ++mi)
                ldsm4(a[mi], Af + swz(rowA[mi], kk * 2 + hiA));
            #pragma unroll
            for (int nb = 0; nb < 2; ++nb) {
                uint32_t b[4];
                ldsm4(b, Bs + swz(rowB[nb], kk * 2 + hiB));
                mma16816(acc[0][2 * nb],     a[0], b[0], b[1]);
                mma16816(acc[0][2 * nb + 1], a[0], b[2], b[3]);
                mma16816(acc[1][2 * nb],     a[1], b[0], b[1]);
                mma16816(acc[1][2 * nb + 1], a[1], b[2], b[3]);
            }
        }
        __syncthreads();
    }

    // epilogue: scale by dinv[row], store out[:, :256]
    int qr = lane >> 2, qc = (lane & 3) * 2;
    #pragma unroll
    for (int mi = 0; mi < 2; ++mi) {
        int r0g = m0 + mi * 16 + qr;
        float dv0 = g_dinv[r0g];
        float dv1 = g_dinv[r0g + 8];
        float* o0 = out + (size_t)r0g * OPITCH;
        float* o1 = o0 + (size_t)8 * OPITCH;
        #pragma unroll
        for (int n8 = 0; n8 < 4; ++n8) {
            int col = warp_n + n8 * 8 + qc;
            o0[col]     = dv0 * acc[mi][n8][0];
            o0[col + 1] = dv0 * acc[mi][n8][1];
            o1[col]     = dv1 * acc[mi][n8][2];
            o1[col + 1] = dv1 * acc[mi][n8][3];
        }
    }
}

// ---------------------------------------------------------------------------
extern "C" void kernel_launch(void* const* d_in, const int* in_sizes, int n_in,
                              void* d_out, int out_size) {
    const float* in = (const float*)d_in[0];
    const float* w  = (const float*)d_in[1];
    float* out = (float*)d_out;

    cudaFuncSetAttribute(support_mma, cudaFuncAttributeMaxDynamicSharedMemorySize, SP_TOTAL);
    cudaFuncSetAttribute(main_gemm2,  cudaFuncAttributeMaxDynamicSharedMemorySize, MG_TOTAL);

    wt_kernel  <<<dim3(16, 8), 256>>>(w);
    colsum_part<<<dim3(8, 64), 256>>>(in);
    finalize_d <<<32, 256>>>();
    support_mma<<<128, 256, SP_TOTAL>>>(in);
    main_gemm2 <<<256, 256, MG_TOTAL>>>(in, out);
}

// round 6
// speedup vs baseline: 5.4226x; 1.0256x over previous
#include <cuda_runtime.h>
#include <cuda_bf16.h>
#include <cstdint>

#define NSMP   8192
#define NA     512
#define DOUT   256
#define PITCH  8712   // input row length
#define ACOL0  512    // A starts at input col 512
#define OPITCH 8448   // output row length

// Scratch (static device globals — no runtime allocation)
__device__ float g_part[64 * NSMP];
__device__ float g_dinv[NSMP];
__device__ __align__(16) __nv_bfloat16 g_supT[(size_t)DOUT * NSMP]; // S_T[n][j]
__device__ __align__(16) __nv_bfloat16 g_WT[(size_t)DOUT * NA];     // W^T[n][k] bf16

// ---------------------------------------------------------------------------
// PTX helpers (base-target-safe)
// ---------------------------------------------------------------------------
__device__ __forceinline__ uint32_t s2u(const void* p) {
    return (uint32_t)__cvta_generic_to_shared(p);
}
__device__ __forceinline__ void cp_async16(uint32_t s, const void* g) {
    asm volatile("cp.async.cg.shared.global [%0], [%1], 16;" :: "r"(s), "l"(g) : "memory");
}
__device__ __forceinline__ void cp_commit() {
    asm volatile("cp.async.commit_group;" ::: "memory");
}
template <int N>
__device__ __forceinline__ void cp_wait() {
    asm volatile("cp.async.wait_group %0;" :: "n"(N) : "memory");
}
__device__ __forceinline__ void ldsm4(uint32_t* r, uint32_t addr) {
    asm volatile("ldmatrix.sync.aligned.m8n8.x4.shared.b16 {%0,%1,%2,%3}, [%4];"
                 : "=r"(r[0]), "=r"(r[1]), "=r"(r[2]), "=r"(r[3]) : "r"(addr));
}
__device__ __forceinline__ void mma16816(float* d, const uint32_t* a, uint32_t b0, uint32_t b1) {
    asm volatile(
        "mma.sync.aligned.m16n8k16.row.col.f32.bf16.bf16.f32 "
        "{%0,%1,%2,%3}, {%4,%5,%6,%7}, {%8,%9}, {%0,%1,%2,%3};"
        : "+f"(d[0]), "+f"(d[1]), "+f"(d[2]), "+f"(d[3])
        : "r"(a[0]), "r"(a[1]), "r"(a[2]), "r"(a[3]), "r"(b0), "r"(b1));
}
// SW128-swizzled smem offset for (row, 16B-chunk c) with 128B rows
__device__ __forceinline__ uint32_t swz(int row, int c) {
    return (uint32_t)(row * 128 + ((c ^ (row & 7)) << 4));
}

// ---------------------------------------------------------------------------
// Kernel: W^T bf16 (tiny, independent)
// ---------------------------------------------------------------------------
__global__ void wt_kernel(const float* __restrict__ w) {
    __shared__ float ts[32][33];
    int k0 = blockIdx.x * 32, n0 = blockIdx.y * 32;
    int t = threadIdx.x;
    int a = t >> 5, b = t & 31;
    #pragma unroll
    for (int i = 0; i < 4; ++i)
        ts[a + 8 * i][b] = w[(size_t)(k0 + a + 8 * i) * DOUT + n0 + b];
    __syncthreads();
    #pragma unroll
    for (int i = 0; i < 4; ++i)
        g_WT[(size_t)(n0 + a + 8 * i) * NA + k0 + b] = __float2bfloat16(ts[b][a + 8 * i]);
}

// ---------------------------------------------------------------------------
// Kernel: partial column sums of A (float4, deterministic)
// ---------------------------------------------------------------------------
__global__ void colsum_part(const float* __restrict__ in) {
    int col = (blockIdx.x * 256 + threadIdx.x) * 4;
    int r0  = blockIdx.y * 128;
    const float* p = in + (size_t)r0 * PITCH + ACOL0 + col;
    float4 s = make_float4(0.f, 0.f, 0.f, 0.f);
    #pragma unroll 8
    for (int r = 0; r < 128; ++r) {
        float4 v = *(const float4*)p;
        s.x += v.x; s.y += v.y; s.z += v.z; s.w += v.w;
        p += PITCH;
    }
    *(float4*)(g_part + blockIdx.y * NSMP + col) = s;
}

__global__ void finalize_d() {
    int col = blockIdx.x * 256 + threadIdx.x;
    float s = 1.0f;
    #pragma unroll
    for (int i = 0; i < 64; ++i) s += g_part[i * NSMP + col];
    g_dinv[col] = rsqrtf(s);
}

// ---------------------------------------------------------------------------
// support (mma.sync): S_T[n][j] = bf16( dinv[j] * (X @ W)[j,n] )
// CTA 64x256, K=512, grid 128. (unchanged from R5 — passed at 18 us)
// ---------------------------------------------------------------------------
#define SP_A0 0
#define SP_B0 8192
#define SP_A1 40960
#define SP_B1 49152
#define SP_TOTAL 81920
#define ST_PITCH 144

__device__ __forceinline__ void sp_load(const float* in, char* smem, int buf, int k0,
                                        int tid, int m0) {
    uint32_t bs = s2u(smem + (buf ? SP_B1 : SP_B0));
    const char* gB = (const char*)g_WT + (size_t)k0 * 2;
    #pragma unroll
    for (int c = 0; c < 8; ++c) {
        int chunk = tid + c * 256;
        int row = chunk >> 3;
        int seg = chunk & 7;
        cp_async16(bs + swz(row, seg), gB + (size_t)row * (NA * 2) + seg * 16);
    }
    cp_commit();
    char* As = smem + (buf ? SP_A1 : SP_A0);
    int f = tid & 15, r0 = tid >> 4;
    #pragma unroll
    for (int i = 0; i < 4; ++i) {
        int row = r0 + 16 * i;
        float4 v = *(const float4*)(in + (size_t)(m0 + row) * PITCH + k0 + f * 4);
        __nv_bfloat162 h0 = __floats2bfloat162_rn(v.x, v.y);
        __nv_bfloat162 h1 = __floats2bfloat162_rn(v.z, v.w);
        *(uint2*)(As + swz(row, f >> 1) + (f & 1) * 8) =
            make_uint2(*(uint32_t*)&h0, *(uint32_t*)&h1);
    }
}

__global__ void __launch_bounds__(256, 1) support_mma(const float* __restrict__ in) {
    extern __shared__ char smem[];
    int tid = threadIdx.x;
    int wid = tid >> 5, lane = tid & 31;
    int m0 = blockIdx.x * 64;
    int warp_m = (wid & 1) * 32;
    int warp_n = (wid >> 1) * 64;

    int rowA[2], rowB[4];
    #pragma unroll
    for (int mi = 0; mi < 2; ++mi) rowA[mi] = warp_m + mi * 16 + (lane & 15);
    int hiA = lane >> 4;
    #pragma unroll
    for (int nb = 0; nb < 4; ++nb)
        rowB[nb] = warp_n + nb * 16 + ((lane >> 4) << 3) + (lane & 7);
    int hiB = (lane >> 3) & 1;

    float acc[2][8][4] = {};

    sp_load(in, smem, 0, 0, tid, m0);
    for (int it = 0; it < NA / 64; ++it) {
        int buf = it & 1;
        if (it + 1 < NA / 64) { sp_load(in, smem, buf ^ 1, (it + 1) * 64, tid, m0); cp_wait<1>(); }
        else cp_wait<0>();
        __syncthreads();
        uint32_t As = s2u(smem + (buf ? SP_A1 : SP_A0));
        uint32_t Bs = s2u(smem + (buf ? SP_B1 : SP_B0));
        #pragma unroll
        for (int kk = 0; kk < 4; ++kk) {
            uint32_t a[2][4];
            #pragma unroll
            for (int mi = 0; mi < 2; ++mi)
                ldsm4(a[mi], As + swz(rowA[mi], kk * 2 + hiA));
            #pragma unroll
            for (int nb = 0; nb < 4; ++nb) {
                uint32_t b[4];
                ldsm4(b, Bs + swz(rowB[nb], kk * 2 + hiB));
                mma16816(acc[0][2 * nb],     a[0], b[0], b[1]);
                mma16816(acc[0][2 * nb + 1], a[0], b[2], b[3]);
                mma16816(acc[1][2 * nb],     a[1], b[0], b[1]);
                mma16816(acc[1][2 * nb + 1], a[1], b[2], b[3]);
            }
        }
        __syncthreads();
    }

    int qr = lane >> 2, qc = (lane & 3) * 2;
    #pragma unroll
    for (int mi = 0; mi < 2; ++mi) {
        int j0 = warp_m + mi * 16 + qr;
        float dv0 = g_dinv[m0 + j0];
        float dv1 = g_dinv[m0 + j0 + 8];
        #pragma unroll
        for (int n8 = 0; n8 < 8; ++n8) {
            int n = warp_n + n8 * 8 + qc;
            *(__nv_bfloat16*)(smem + n * ST_PITCH + j0 * 2)             = __float2bfloat16(dv0 * acc[mi][n8][0]);
            *(__nv_bfloat16*)(smem + (n + 1) * ST_PITCH + j0 * 2)       = __float2bfloat16(dv0 * acc[mi][n8][1]);
            *(__nv_bfloat16*)(smem + n * ST_PITCH + (j0 + 8) * 2)       = __float2bfloat16(dv1 * acc[mi][n8][2]);
            *(__nv_bfloat16*)(smem + (n + 1) * ST_PITCH + (j0 + 8) * 2) = __float2bfloat16(dv1 * acc[mi][n8][3]);
        }
    }
    __syncthreads();
    #pragma unroll
    for (int c = 0; c < 8; ++c) {
        int chunk = tid + c * 256;
        int n = chunk >> 3;
        int seg = chunk & 7;
        uint4 v = *(const uint4*)(smem + n * ST_PITCH + seg * 16);
        *(uint4*)((char*)g_supT + ((size_t)n * NSMP + m0) * 2 + seg * 16) = v;
    }
}

// ---------------------------------------------------------------------------
// main (mma.sync): out[:, :256] = diag(dinv) * (A+I) @ S ; out[:, 256:] = A+I
// CTA 64x256, grid 128, 3-stage cp.async ring, ONE __syncthreads per iter.
// ---------------------------------------------------------------------------
#define MGS_STRIDE 49152   // per-stage: B(32KB) + Araw(16KB)
#define MGS_AOFF   32768
#define MG_AF      147456  // bf16 A, 2 x 8KB
#define MG3_TOTAL  163840

__device__ __forceinline__ void mg3_load(const float* in, char* smem, int stage, int k0,
                                         int tid, int m0) {
    // B tile: 256 x 64 bf16 from g_supT
    uint32_t bs = s2u(smem + stage * MGS_STRIDE);
    const char* gB = (const char*)g_supT + (size_t)k0 * 2;
    #pragma unroll
    for (int c = 0; c < 8; ++c) {
        int chunk = tid + c * 256;
        int row = chunk >> 3;
        int seg = chunk & 7;
        cp_async16(bs + swz(row, seg), gB + (size_t)row * (NSMP * 2) + seg * 16);
    }
    // A raw fp32 tile 64x64 (16KB): thread owns row tid>>2, chunks (tid&3)+4i
    uint32_t ar = s2u(smem + stage * MGS_STRIDE + MGS_AOFF);
    int r = tid >> 2, cb = tid & 3;
    const char* gA = (const char*)(in + (size_t)(m0 + r) * PITCH + ACOL0 + k0);
    #pragma unroll
    for (int i = 0; i < 4; ++i) {
        int ci = cb + 4 * i;
        cp_async16(ar + r * 256 + ((ci ^ (r & 15)) << 4), gA + ci * 16);
    }
    cp_commit();
}

__global__ void __launch_bounds__(256, 1) main_gemm3(const float* __restrict__ in,
                                                     float* __restrict__ out) {
    extern __shared__ char smem[];
    int tid = threadIdx.x;
    int wid = tid >> 5, lane = tid & 31;
    int m0 = blockIdx.x * 64;
    int warp_m = (wid & 1) * 32;
    int warp_n = (wid >> 1) * 64;

    int rowA[2], rowB[4];
    #pragma unroll
    for (int mi = 0; mi < 2; ++mi) rowA[mi] = warp_m + mi * 16 + (lane & 15);
    int hiA = lane >> 4;
    #pragma unroll
    for (int nb = 0; nb < 4; ++nb)
        rowB[nb] = warp_n + nb * 16 + ((lane >> 4) << 3) + (lane & 7);
    int hiB = (lane >> 3) & 1;

    float acc[2][8][4] = {};

    int pr = tid >> 2, pc = tid & 3;   // processA mapping (must match mg3_load)
    float* aog = out + (size_t)(m0 + pr) * OPITCH + DOUT;

    mg3_load(in, smem, 0, 0, tid, m0);
    mg3_load(in, smem, 1, 64, tid, m0);

    for (int it = 0; it < NSMP / 64; ++it) {
        int stage = it % 3;
        int k0 = it * 64;
        if (it == NSMP / 64 - 1) cp_wait<0>(); else cp_wait<1>();

        // processA: own raw fp32 -> +I -> fused A+I copy-out -> bf16 swizzled STS
        {
            const char* ar = smem + stage * MGS_STRIDE + MGS_AOFF;
            char* af = smem + MG_AF + (it & 1) * 8192;
            int grow = m0 + pr;
            #pragma unroll
            for (int i = 0; i < 4; ++i) {
                int ci = pc + 4 * i;
                float4 v = *(const float4*)(ar + pr * 256 + ((ci ^ (pr & 15)) << 4));
                int d = grow - (k0 + ci * 4);
                if ((unsigned)d < 4u) ((float*)&v)[d] += 1.f;
                *(float4*)(aog + k0 + ci * 4) = v;
                __nv_bfloat162 h0 = __floats2bfloat162_rn(v.x, v.y);
                __nv_bfloat162 h1 = __floats2bfloat162_rn(v.z, v.w);
                *(uint2*)(af + swz(pr, ci >> 1) + (ci & 1) * 8) =
                    make_uint2(*(uint32_t*)&h0, *(uint32_t*)&h1);
            }
        }
        __syncthreads();

        if (it + 2 < NSMP / 64) mg3_load(in, smem, (it + 2) % 3, (it + 2) * 64, tid, m0);

        uint32_t Af = s2u(smem + MG_AF + (it & 1) * 8192);
        uint32_t Bs = s2u(smem + stage * MGS_STRIDE);
        #pragma unroll
        for (int kk = 0; kk < 4; ++kk) {
            uint32_t a[2][4];
            #pragma unroll
            for (int mi = 0; mi < 2; ++mi)
                ldsm4(a[mi], Af + swz(rowA[mi], kk * 2 + hiA));
            #pragma unroll
            for (int nb = 0; nb < 4; ++nb) {
                uint32_t b[4];
                ldsm4(b, Bs + swz(rowB[nb], kk * 2 + hiB));
                mma16816(acc[0][2 * nb],     a[0], b[0], b[1]);
                mma16816(acc[0][2 * nb + 1], a[0], b[2], b[3]);
                mma16816(acc[1][2 * nb],     a[1], b[0], b[1]);
                mma16816(acc[1][2 * nb + 1], a[1], b[2], b[3]);
            }
        }
    }

    // epilogue: scale by dinv[row], store out[:, :256]
    int qr = lane >> 2, qc = (lane & 3) * 2;
    #pragma unroll
    for (int mi = 0; mi < 2; ++mi) {
        int r0g = m0 + warp_m + mi * 16 + qr;
        float dv0 = g_dinv[r0g];
        float dv1 = g_dinv[r0g + 8];
        float* o0 = out + (size_t)r0g * OPITCH;
        float* o1 = o0 + (size_t)8 * OPITCH;
        #pragma unroll
        for (int n8 = 0; n8 < 8; ++n8) {
            int col = warp_n + n8 * 8 + qc;
            o0[col]     = dv0 * acc[mi][n8][0];
            o0[col + 1] = dv0 * acc[mi][n8][1];
            o1[col]     = dv1 * acc[mi][n8][2];
            o1[col + 1] = dv1 * acc[mi][n8][3];
        }
    }
}

// ---------------------------------------------------------------------------
extern "C" void kernel_launch(void* const* d_in, const int* in_sizes, int n_in,
                              void* d_out, int out_size) {
    const float* in = (const float*)d_in[0];
    const float* w  = (const float*)d_in[1];
    float* out = (float*)d_out;

    cudaFuncSetAttribute(support_mma, cudaFuncAttributeMaxDynamicSharedMemorySize, SP_TOTAL);
    cudaFuncSetAttribute(main_gemm3,  cudaFuncAttributeMaxDynamicSharedMemorySize, MG3_TOTAL);

    wt_kernel  <<<dim3(16, 8), 256>>>(w);
    colsum_part<<<dim3(8, 64), 256>>>(in);
    finalize_d <<<32, 256>>>();
    support_mma<<<128, 256, SP_TOTAL>>>(in);
    main_gemm3 <<<128, 256, MG3_TOTAL>>>(in, out);
}